// round 13
// baseline (speedup 1.0000x reference)
#include <cuda_runtime.h>
#include <cuda_bf16.h>
#include <math.h>

#define NN 100000
#define EE 3200000

// ---- scratch (device globals; allocation-free) ----
// Invariant at entry (restored each run -> replay-deterministic):
//   g_deg, g_acc1, g_acc2 all-zero.
__device__ int    g_deg[NN];
__device__ int2   g_edge[EE];    // packed (src, dst)
__device__ float  g_dinv[NN];
__device__ float4 g_xw[NN];      // raw x @ W1
__device__ float4 g_y[NN];       // dinv * xw
__device__ float4 g_z[NN];       // dinv * (relu(conv1) @ [Wmu|Wls])
__device__ float4 g_acc1[NN];
__device__ float4 g_acc2[NN];

// ---- fused: edge decode+histogram blocks interleaved with gemm blocks ----
__global__ void __launch_bounds__(256) k_fused(const float* __restrict__ x,
                                               const float* __restrict__ W1,
                                               const void* __restrict__ ei,
                                               int n, int e,
                                               int ebk, int gbk) {
    __shared__ float4 Ws[512];
    __shared__ int s_flag;
    int b = blockIdx.x;
    int t = threadIdx.x;

    int edgeB, gemmB;   // role + role-local block id
    if (gbk == 2 * ebk) {
        int r = b % 3;
        if (r == 0) { edgeB = b / 3; gemmB = -1; }
        else        { edgeB = -1;    gemmB = (b / 3) * 2 + (r - 1); }
    } else {
        if (b < ebk) { edgeB = b; gemmB = -1; }
        else         { edgeB = -1; gemmB = b - ebk; }
    }

    if (edgeB >= 0) {
        // ---- parallel dtype detect: 64 concurrent loads, shared-flag reduce ----
        if (t == 0) s_flag = 0;
        __syncthreads();
        if (t < 64 && ((const unsigned*)ei)[2 * t + 1] != 0u) atomicOr(&s_flag, 1);
        __syncthreads();
        int is64 = !s_flag;      // int64 LE, ids < 2^31 => odd words all zero

        int i = edgeB * 256 + t;
        int npair = e >> 1;
        if (i < npair) {
            int s0, s1, d0, d1;
            if (is64) {
                const longlong2* ps = (const longlong2*)ei;
                const longlong2* pd = (const longlong2*)((const long long*)ei + e);
                longlong2 sv = __ldg(&ps[i]);
                longlong2 dv = __ldg(&pd[i]);
                s0 = (int)sv.x; s1 = (int)sv.y; d0 = (int)dv.x; d1 = (int)dv.y;
            } else {
                const int2* ps = (const int2*)ei;
                const int2* pd = (const int2*)((const int*)ei + e);
                int2 sv = __ldg(&ps[i]);
                int2 dv = __ldg(&pd[i]);
                s0 = sv.x; s1 = sv.y; d0 = dv.x; d1 = dv.y;
            }
            ((int4*)g_edge)[i] = make_int4(s0, d0, s1, d1);
            atomicAdd(&g_deg[d0], 1);       // g_deg pre-zeroed by invariant
            atomicAdd(&g_deg[d1], 1);
        }
        if (i == 0 && (e & 1)) {            // odd tail (E even in practice)
            int s, d;
            if (is64) {
                const long long* p = (const long long*)ei;
                s = (int)p[e - 1]; d = (int)p[2 * (long long)e - 1];
            } else {
                const int* p = (const int*)ei;
                s = p[e - 1]; d = p[2 * e - 1];
            }
            g_edge[e - 1] = make_int2(s, d);
            atomicAdd(&g_deg[d], 1);
        }
    } else {
        // ---------------- gemm work ----------------
        const float4* W4 = (const float4*)W1;
        Ws[t]       = __ldg(&W4[t]);
        Ws[t + 256] = __ldg(&W4[t + 256]);
        __syncthreads();

        int warp = t >> 5, lane = t & 31;
        int row  = gemmB * 8 + warp;
        if (row >= n) return;

        const float4* xr = (const float4*)(x + (size_t)row * 512);
        float4 acc = make_float4(0.f, 0.f, 0.f, 0.f);
        #pragma unroll
        for (int i = 0; i < 4; ++i) {
            float4 xv = __ldg(&xr[i * 32 + lane]);
            int k = i * 128 + lane * 4;
            float4 w0 = Ws[k], w1 = Ws[k + 1], w2 = Ws[k + 2], w3 = Ws[k + 3];
            acc.x += xv.x * w0.x + xv.y * w1.x + xv.z * w2.x + xv.w * w3.x;
            acc.y += xv.x * w0.y + xv.y * w1.y + xv.z * w2.y + xv.w * w3.y;
            acc.z += xv.x * w0.z + xv.y * w1.z + xv.z * w2.z + xv.w * w3.z;
            acc.w += xv.x * w0.w + xv.y * w1.w + xv.z * w2.w + xv.w * w3.w;
        }
        #pragma unroll
        for (int off = 16; off; off >>= 1) {
            acc.x += __shfl_xor_sync(0xffffffffu, acc.x, off);
            acc.y += __shfl_xor_sync(0xffffffffu, acc.y, off);
            acc.z += __shfl_xor_sync(0xffffffffu, acc.z, off);
            acc.w += __shfl_xor_sync(0xffffffffu, acc.w, off);
        }
        if (lane == 0) g_xw[row] = acc;
    }
    // implicit PDL trigger at kernel completion
}

// ---- y: dinv + y = dinv*xw; reset deg. Sync at top (no live state held). ----
__global__ void k_y(int n) {
    cudaGridDependencySynchronize();
    int i = blockIdx.x * blockDim.x + threadIdx.x;
    if (i >= n) return;
    float di = rsqrtf((float)(g_deg[i] + 1));
    g_deg[i] = 0;                       // restore invariant
    g_dinv[i] = di;
    float4 v = g_xw[i];
    g_y[i] = make_float4(di * v.x, di * v.y, di * v.z, di * v.w);
}

// ---- conv1 scatter: 4 edges/thread (R7-proven body) ----
__global__ void __launch_bounds__(256) k_conv1(int e) {
    cudaGridDependencySynchronize();
    int i = blockIdx.x * blockDim.x + threadIdx.x;
    int base = i * 4;
    if (base >= e) return;
    if (base + 3 < e) {
        int4 a = ((const int4*)g_edge)[i * 2];
        int4 b = ((const int4*)g_edge)[i * 2 + 1];
        float4 v0 = g_y[a.x];
        float4 v1 = g_y[a.z];
        float4 v2 = g_y[b.x];
        float4 v3 = g_y[b.z];
        atomicAdd(&g_acc1[a.y], v0);    // acc1 zero by invariant
        atomicAdd(&g_acc1[a.w], v1);
        atomicAdd(&g_acc1[b.y], v2);
        atomicAdd(&g_acc1[b.w], v3);
    } else {
        for (int j = base; j < e; ++j) {
            int2 ed = g_edge[j];
            atomicAdd(&g_acc1[ed.y], g_y[ed.x]);
        }
    }
}

// ---- fin1: h = relu(di*(acc1+y)+b1); z = di*(h@[Wmu|Wls]); reset acc1 ----
__global__ void k_fin1(const float* __restrict__ b1,
                       const float* __restrict__ Wmu,
                       const float* __restrict__ Wls, int n) {
    cudaGridDependencySynchronize();
    int i = blockIdx.x * blockDim.x + threadIdx.x;
    if (i >= n) return;
    float di = g_dinv[i];
    float4 a = g_acc1[i];
    g_acc1[i] = make_float4(0.f, 0.f, 0.f, 0.f);   // restore invariant
    float4 y = g_y[i];
    float h0 = fmaxf(di * (a.x + y.x) + __ldg(&b1[0]), 0.f);
    float h1 = fmaxf(di * (a.y + y.y) + __ldg(&b1[1]), 0.f);
    float h2 = fmaxf(di * (a.z + y.z) + __ldg(&b1[2]), 0.f);
    float h3 = fmaxf(di * (a.w + y.w) + __ldg(&b1[3]), 0.f);
    float4 o;   // W_mu, W_ls: [4,2] row-major
    o.x = h0 * __ldg(&Wmu[0]) + h1 * __ldg(&Wmu[2]) + h2 * __ldg(&Wmu[4]) + h3 * __ldg(&Wmu[6]);
    o.y = h0 * __ldg(&Wmu[1]) + h1 * __ldg(&Wmu[3]) + h2 * __ldg(&Wmu[5]) + h3 * __ldg(&Wmu[7]);
    o.z = h0 * __ldg(&Wls[0]) + h1 * __ldg(&Wls[2]) + h2 * __ldg(&Wls[4]) + h3 * __ldg(&Wls[6]);
    o.w = h0 * __ldg(&Wls[1]) + h1 * __ldg(&Wls[3]) + h2 * __ldg(&Wls[5]) + h3 * __ldg(&Wls[7]);
    g_z[i] = make_float4(di * o.x, di * o.y, di * o.z, di * o.w);
}

// ---- conv2 scatter: 4 edges/thread ----
__global__ void __launch_bounds__(256) k_conv2(int e) {
    cudaGridDependencySynchronize();
    int i = blockIdx.x * blockDim.x + threadIdx.x;
    int base = i * 4;
    if (base >= e) return;
    if (base + 3 < e) {
        int4 a = ((const int4*)g_edge)[i * 2];
        int4 b = ((const int4*)g_edge)[i * 2 + 1];
        float4 v0 = g_z[a.x];
        float4 v1 = g_z[a.z];
        float4 v2 = g_z[b.x];
        float4 v3 = g_z[b.z];
        atomicAdd(&g_acc2[a.y], v0);    // acc2 zero by invariant
        atomicAdd(&g_acc2[a.w], v1);
        atomicAdd(&g_acc2[b.y], v2);
        atomicAdd(&g_acc2[b.w], v3);
    } else {
        for (int j = base; j < e; ++j) {
            int2 ed = g_edge[j];
            atomicAdd(&g_acc2[ed.y], g_z[ed.x]);
        }
    }
}

// ---- fin2: out = di*(acc2+z) + bias; reset acc2 ----
__global__ void k_fin2(const float* __restrict__ bmu,
                       const float* __restrict__ bls,
                       float* __restrict__ out, int n) {
    cudaGridDependencySynchronize();
    int i = blockIdx.x * blockDim.x + threadIdx.x;
    if (i >= n) return;
    float di = g_dinv[i];
    float4 a = g_acc2[i];
    g_acc2[i] = make_float4(0.f, 0.f, 0.f, 0.f);   // restore invariant
    float4 z = g_z[i];
    float2 mu, ls;
    mu.x = di * (a.x + z.x) + __ldg(&bmu[0]);
    mu.y = di * (a.y + z.y) + __ldg(&bmu[1]);
    ls.x = di * (a.z + z.z) + __ldg(&bls[0]);
    ls.y = di * (a.w + z.w) + __ldg(&bls[1]);
    ((float2*)out)[i] = mu;                       // mu [N,2]
    ((float2*)(out + 2 * (size_t)n))[i] = ls;     // logstd [N,2]
}

// ---- PDL launch helper ----
template <typename F, typename... Args>
static void pdl(int grid, F f, Args... args) {
    cudaLaunchConfig_t cfg = {};
    cfg.gridDim  = dim3((unsigned)grid, 1, 1);
    cfg.blockDim = dim3(256, 1, 1);
    cfg.dynamicSmemBytes = 0;
    cfg.stream = 0;
    cudaLaunchAttribute at[1];
    at[0].id = cudaLaunchAttributeProgrammaticStreamSerialization;
    at[0].val.programmaticStreamSerializationAllowed = 1;
    cfg.attrs = at;
    cfg.numAttrs = 1;
    cudaLaunchKernelEx(&cfg, f, args...);
}

extern "C" void kernel_launch(void* const* d_in, const int* in_sizes, int n_in,
                              void* d_out, int out_size) {
    const float* x   = (const float*)d_in[0];
    const void*  ei  = d_in[1];
    const float* W1  = (const float*)d_in[2];
    const float* b1  = (const float*)d_in[3];
    const float* Wmu = (const float*)d_in[4];
    const float* bmu = (const float*)d_in[5];
    const float* Wls = (const float*)d_in[6];
    const float* bls = (const float*)d_in[7];

    int n = in_sizes[0] / 512;   // 100000
    int e = in_sizes[1] / 2;     // 3200000

    int nb  = (n + 255) / 256;
    int ebk = ((e >> 1) + 255) / 256;     // edge-pair blocks  (6250)
    int gbk = (n + 7) / 8;                // gemm blocks       (12500)
    int qb  = ((e + 3) / 4 + 255) / 256;  // conv edge-quad blocks

    pdl(ebk + gbk, k_fused, x, W1, ei, n, e, ebk, gbk);   // edges ∥ gemm
    pdl(nb,        k_y, n);
    pdl(qb,        k_conv1, e);
    pdl(nb,        k_fin1, b1, Wmu, Wls, n);
    pdl(qb,        k_conv2, e);
    pdl(nb,        k_fin2, bmu, bls, (float*)d_out, n);
}

// round 14
// speedup vs baseline: 1.0243x; 1.0243x over previous
#include <cuda_runtime.h>
#include <cuda_bf16.h>
#include <math.h>

#define NN 100000
#define EE 3200000

// ---- scratch (device globals; allocation-free) ----
// Reset schedule (replay-deterministic):
//   deg  : consumed by k_y, zeroed in k_conv1 (post-sync)
//   acc1 : consumed by k_fin1, zeroed in k_conv2 (post-sync)
//   acc2 : consumed by k_fin2, zeroed in next run's k_conv1 (pre-sync)
__device__ int    g_deg[NN];
__device__ int2   g_edge[EE];    // packed (src, dst)
__device__ float  g_dinv[NN];
__device__ float4 g_xw[NN];      // raw x @ W1
__device__ float4 g_y[NN];       // dinv * xw
__device__ float4 g_z[NN];       // dinv * (relu(conv1) @ [Wmu|Wls])
__device__ float4 g_acc1[NN];
__device__ float4 g_acc2[NN];

// ---- fused: edge decode+histogram blocks interleaved with gemm blocks ----
__global__ void __launch_bounds__(256) k_fused(const float* __restrict__ x,
                                               const float* __restrict__ W1,
                                               const void* __restrict__ ei,
                                               int n, int e,
                                               int ebk, int gbk) {
    __shared__ float4 Ws[512];
    __shared__ int s_flag;
    int b = blockIdx.x;
    int t = threadIdx.x;

    int edgeB, gemmB;   // role + role-local block id
    if (gbk == 2 * ebk) {
        int r = b % 3;
        if (r == 0) { edgeB = b / 3; gemmB = -1; }
        else        { edgeB = -1;    gemmB = (b / 3) * 2 + (r - 1); }
    } else {
        if (b < ebk) { edgeB = b; gemmB = -1; }
        else         { edgeB = -1; gemmB = b - ebk; }
    }

    if (edgeB >= 0) {
        // ---- parallel dtype detect: 64 concurrent loads, shared-flag reduce ----
        if (t == 0) s_flag = 0;
        __syncthreads();
        if (t < 64 && ((const unsigned*)ei)[2 * t + 1] != 0u) atomicOr(&s_flag, 1);
        __syncthreads();
        int is64 = !s_flag;      // int64 LE, ids < 2^31 => odd words all zero

        int i = edgeB * 256 + t;
        int npair = e >> 1;
        if (i < npair) {
            int s0, s1, d0, d1;
            if (is64) {
                const longlong2* ps = (const longlong2*)ei;
                const longlong2* pd = (const longlong2*)((const long long*)ei + e);
                longlong2 sv = __ldg(&ps[i]);
                longlong2 dv = __ldg(&pd[i]);
                s0 = (int)sv.x; s1 = (int)sv.y; d0 = (int)dv.x; d1 = (int)dv.y;
            } else {
                const int2* ps = (const int2*)ei;
                const int2* pd = (const int2*)((const int*)ei + e);
                int2 sv = __ldg(&ps[i]);
                int2 dv = __ldg(&pd[i]);
                s0 = sv.x; s1 = sv.y; d0 = dv.x; d1 = dv.y;
            }
            ((int4*)g_edge)[i] = make_int4(s0, d0, s1, d1);
            atomicAdd(&g_deg[d0], 1);       // g_deg zeroed by prior run's conv1
            atomicAdd(&g_deg[d1], 1);
        }
        if (i == 0 && (e & 1)) {            // odd tail (E even in practice)
            int s, d;
            if (is64) {
                const long long* p = (const long long*)ei;
                s = (int)p[e - 1]; d = (int)p[2 * (long long)e - 1];
            } else {
                const int* p = (const int*)ei;
                s = p[e - 1]; d = p[2 * e - 1];
            }
            g_edge[e - 1] = make_int2(s, d);
            atomicAdd(&g_deg[d], 1);
        }
    } else {
        // ---------------- gemm work ----------------
        const float4* W4 = (const float4*)W1;
        Ws[t]       = __ldg(&W4[t]);
        Ws[t + 256] = __ldg(&W4[t + 256]);
        __syncthreads();

        int warp = t >> 5, lane = t & 31;
        int row  = gemmB * 8 + warp;
        if (row >= n) return;

        const float4* xr = (const float4*)(x + (size_t)row * 512);
        float4 acc = make_float4(0.f, 0.f, 0.f, 0.f);
        #pragma unroll
        for (int i = 0; i < 4; ++i) {
            float4 xv = __ldg(&xr[i * 32 + lane]);
            int k = i * 128 + lane * 4;
            float4 w0 = Ws[k], w1 = Ws[k + 1], w2 = Ws[k + 2], w3 = Ws[k + 3];
            acc.x += xv.x * w0.x + xv.y * w1.x + xv.z * w2.x + xv.w * w3.x;
            acc.y += xv.x * w0.y + xv.y * w1.y + xv.z * w2.y + xv.w * w3.y;
            acc.z += xv.x * w0.z + xv.y * w1.z + xv.z * w2.z + xv.w * w3.z;
            acc.w += xv.x * w0.w + xv.y * w1.w + xv.z * w2.w + xv.w * w3.w;
        }
        #pragma unroll
        for (int off = 16; off; off >>= 1) {
            acc.x += __shfl_xor_sync(0xffffffffu, acc.x, off);
            acc.y += __shfl_xor_sync(0xffffffffu, acc.y, off);
            acc.z += __shfl_xor_sync(0xffffffffu, acc.z, off);
            acc.w += __shfl_xor_sync(0xffffffffu, acc.w, off);
        }
        if (lane == 0) g_xw[row] = acc;
    }
}

// ---- y: dinv = rsqrt(deg+1); y = dinv*xw. Pure compute (no resets). ----
__global__ void k_y(int n) {
    cudaGridDependencySynchronize();
    int i = blockIdx.x * blockDim.x + threadIdx.x;
    if (i >= n) return;
    float di = rsqrtf((float)(g_deg[i] + 1));
    g_dinv[i] = di;
    float4 v = g_xw[i];
    g_y[i] = make_float4(di * v.x, di * v.y, di * v.z, di * v.w);
}

// ---- conv1: pre-sync acc2 reset; post-sync deg reset + 4-edge scatter ----
__global__ void __launch_bounds__(256) k_conv1(int e, int n) {
    int i = blockIdx.x * blockDim.x + threadIdx.x;
    // acc2 reset pre-sync: last reader was previous run's fin2 (complete);
    // k_y (running concurrently) never touches acc2.
    if (i < n) g_acc2[i] = make_float4(0.f, 0.f, 0.f, 0.f);
    cudaGridDependencySynchronize();
    if (i < n) g_deg[i] = 0;            // post-sync: k_y has consumed deg
    int base = i * 4;
    if (base >= e) return;
    if (base + 3 < e) {
        int4 a = ((const int4*)g_edge)[i * 2];
        int4 b = ((const int4*)g_edge)[i * 2 + 1];
        float4 v0 = g_y[a.x];
        float4 v1 = g_y[a.z];
        float4 v2 = g_y[b.x];
        float4 v3 = g_y[b.z];
        atomicAdd(&g_acc1[a.y], v0);    // acc1 zeroed by prior run's conv2
        atomicAdd(&g_acc1[a.w], v1);
        atomicAdd(&g_acc1[b.y], v2);
        atomicAdd(&g_acc1[b.w], v3);
    } else {
        for (int j = base; j < e; ++j) {
            int2 ed = g_edge[j];
            atomicAdd(&g_acc1[ed.y], g_y[ed.x]);
        }
    }
}

// ---- fin1: pure compute: h = relu(di*(acc1+y)+b1); z = di*(h@[Wmu|Wls]) ----
__global__ void k_fin1(const float* __restrict__ b1,
                       const float* __restrict__ Wmu,
                       const float* __restrict__ Wls, int n) {
    cudaGridDependencySynchronize();
    int i = blockIdx.x * blockDim.x + threadIdx.x;
    if (i >= n) return;
    float di = g_dinv[i];
    float4 a = g_acc1[i];
    float4 y = g_y[i];
    float h0 = fmaxf(di * (a.x + y.x) + __ldg(&b1[0]), 0.f);
    float h1 = fmaxf(di * (a.y + y.y) + __ldg(&b1[1]), 0.f);
    float h2 = fmaxf(di * (a.z + y.z) + __ldg(&b1[2]), 0.f);
    float h3 = fmaxf(di * (a.w + y.w) + __ldg(&b1[3]), 0.f);
    float4 o;   // W_mu, W_ls: [4,2] row-major
    o.x = h0 * __ldg(&Wmu[0]) + h1 * __ldg(&Wmu[2]) + h2 * __ldg(&Wmu[4]) + h3 * __ldg(&Wmu[6]);
    o.y = h0 * __ldg(&Wmu[1]) + h1 * __ldg(&Wmu[3]) + h2 * __ldg(&Wmu[5]) + h3 * __ldg(&Wmu[7]);
    o.z = h0 * __ldg(&Wls[0]) + h1 * __ldg(&Wls[2]) + h2 * __ldg(&Wls[4]) + h3 * __ldg(&Wls[6]);
    o.w = h0 * __ldg(&Wls[1]) + h1 * __ldg(&Wls[3]) + h2 * __ldg(&Wls[5]) + h3 * __ldg(&Wls[7]);
    g_z[i] = make_float4(di * o.x, di * o.y, di * o.z, di * o.w);
}

// ---- conv2: post-sync acc1 reset + 4-edge scatter ----
__global__ void __launch_bounds__(256) k_conv2(int e, int n) {
    cudaGridDependencySynchronize();
    int i = blockIdx.x * blockDim.x + threadIdx.x;
    if (i < n) g_acc1[i] = make_float4(0.f, 0.f, 0.f, 0.f);   // fin1 has read acc1
    int base = i * 4;
    if (base >= e) return;
    if (base + 3 < e) {
        int4 a = ((const int4*)g_edge)[i * 2];
        int4 b = ((const int4*)g_edge)[i * 2 + 1];
        float4 v0 = g_z[a.x];
        float4 v1 = g_z[a.z];
        float4 v2 = g_z[b.x];
        float4 v3 = g_z[b.z];
        atomicAdd(&g_acc2[a.y], v0);    // acc2 zeroed by this run's conv1
        atomicAdd(&g_acc2[a.w], v1);
        atomicAdd(&g_acc2[b.y], v2);
        atomicAdd(&g_acc2[b.w], v3);
    } else {
        for (int j = base; j < e; ++j) {
            int2 ed = g_edge[j];
            atomicAdd(&g_acc2[ed.y], g_z[ed.x]);
        }
    }
}

// ---- fin2: pure compute: out = di*(acc2+z) + bias ----
__global__ void k_fin2(const float* __restrict__ bmu,
                       const float* __restrict__ bls,
                       float* __restrict__ out, int n) {
    cudaGridDependencySynchronize();
    int i = blockIdx.x * blockDim.x + threadIdx.x;
    if (i >= n) return;
    float di = g_dinv[i];
    float4 a = g_acc2[i];
    float4 z = g_z[i];
    float2 mu, ls;
    mu.x = di * (a.x + z.x) + __ldg(&bmu[0]);
    mu.y = di * (a.y + z.y) + __ldg(&bmu[1]);
    ls.x = di * (a.z + z.z) + __ldg(&bls[0]);
    ls.y = di * (a.w + z.w) + __ldg(&bls[1]);
    ((float2*)out)[i] = mu;                       // mu [N,2]
    ((float2*)(out + 2 * (size_t)n))[i] = ls;     // logstd [N,2]
}

// ---- PDL launch helper ----
template <typename F, typename... Args>
static void pdl(int grid, F f, Args... args) {
    cudaLaunchConfig_t cfg = {};
    cfg.gridDim  = dim3((unsigned)grid, 1, 1);
    cfg.blockDim = dim3(256, 1, 1);
    cfg.dynamicSmemBytes = 0;
    cfg.stream = 0;
    cudaLaunchAttribute at[1];
    at[0].id = cudaLaunchAttributeProgrammaticStreamSerialization;
    at[0].val.programmaticStreamSerializationAllowed = 1;
    cfg.attrs = at;
    cfg.numAttrs = 1;
    cudaLaunchKernelEx(&cfg, f, args...);
}

extern "C" void kernel_launch(void* const* d_in, const int* in_sizes, int n_in,
                              void* d_out, int out_size) {
    const float* x   = (const float*)d_in[0];
    const void*  ei  = d_in[1];
    const float* W1  = (const float*)d_in[2];
    const float* b1  = (const float*)d_in[3];
    const float* Wmu = (const float*)d_in[4];
    const float* bmu = (const float*)d_in[5];
    const float* Wls = (const float*)d_in[6];
    const float* bls = (const float*)d_in[7];

    int n = in_sizes[0] / 512;   // 100000
    int e = in_sizes[1] / 2;     // 3200000

    int nb  = (n + 255) / 256;
    int ebk = ((e >> 1) + 255) / 256;     // edge-pair blocks  (6250)
    int gbk = (n + 7) / 8;                // gemm blocks       (12500)
    int qb  = ((e + 3) / 4 + 255) / 256;  // conv edge-quad blocks

    pdl(ebk + gbk, k_fused, x, W1, ei, n, e, ebk, gbk);   // edges ∥ gemm
    pdl(nb,        k_y, n);
    pdl(qb,        k_conv1, e, n);
    pdl(nb,        k_fin1, b1, Wmu, Wls, n);
    pdl(qb,        k_conv2, e, n);
    pdl(nb,        k_fin2, bmu, bls, (float*)d_out, n);
}